// round 15
// baseline (speedup 1.0000x reference)
#include <cuda_runtime.h>
#include <cuda_fp16.h>
#include <cstdint>

#define T_STEPS 30
#define BATCH   16384
#define NP      7
#define MROWS   64
#define NTHREADS 1024
#define NCTAS   (BATCH / MROWS)     // 256

#define BSTR    208                 // B row stride bytes (104 halves), conflict-free ldsm
#define ASTR    240                 // A(h) row stride bytes (120 halves), conflict-free ldsm
                                    // A cols 102..119 stay ZERO -> annihilate B overread in ch6

// smem byte offsets
#define SM_B   0                    // B: 400 x 208 = 83200 (single fp16 plane)
#define SM_A   83200                // A parity buffers: [A0|A1], each 64*240=15360
#define ABUF   15360
#define SM_W2  113920               // full W2 staged: 4900 floats = 19600
#define SM_X   133520               // staged x: 31 x 64 fp16 = 3968 (slot 30 = 0)
#define SMEM_BYTES 137488

// ---- device scratch (allocation-free) ----
__device__ float g_v1[400];                  // Wih1 @ W1
__device__ float g_u1[400];                  // Wih1 @ b1 + bih1 + bhh1
__device__ uint2 g_in2[(size_t)NCTAS * NTHREADS * 7];   // layer-2 pre-acts, packed fp16 frag

// ============================ helpers ============================
__device__ __forceinline__ uint32_t sptr(const void* p) {
    uint32_t a;
    asm("{ .reg .u64 t; cvta.to.shared.u64 t, %1; cvt.u32.u64 %0, t; }" : "=r"(a) : "l"(p));
    return a;
}
__device__ __forceinline__ float tanha(float x) {
    float y; asm("tanh.approx.f32 %0, %1;" : "=f"(y) : "f"(x)); return y;
}
__device__ __forceinline__ float sigf(float x) { return fmaf(tanha(0.5f * x), 0.5f, 0.5f); }

__device__ __forceinline__ void ldsm_x4(uint32_t* r, uint32_t a) {
    asm volatile("ldmatrix.sync.aligned.m8n8.x4.shared.b16 {%0,%1,%2,%3}, [%4];"
                 : "=r"(r[0]), "=r"(r[1]), "=r"(r[2]), "=r"(r[3]) : "r"(a));
}
__device__ __forceinline__ void ldsm_x2(uint32_t* r, uint32_t a) {
    asm volatile("ldmatrix.sync.aligned.m8n8.x2.shared.b16 {%0,%1}, [%2];"
                 : "=r"(r[0]), "=r"(r[1]) : "r"(a));
}
// fp16-accumulator MMA: D,C are 2 regs (packed halves)
__device__ __forceinline__ void mma_f16acc(uint32_t* d, const uint32_t* a, const uint32_t* b) {
    asm volatile("mma.sync.aligned.m16n8k16.row.col.f16.f16.f16.f16 "
                 "{%0,%1}, {%2,%3,%4,%5}, {%6,%7}, {%0,%1};"
                 : "+r"(d[0]), "+r"(d[1])
                 : "r"(a[0]), "r"(a[1]), "r"(a[2]), "r"(a[3]), "r"(b[0]), "r"(b[1]));
}

// ============================ precompute (tiny) ============================
__global__ void precompute_kernel(const float* __restrict__ W1,
                                  const float* __restrict__ b1,
                                  const float* __restrict__ Wih1,
                                  const float* __restrict__ bih1,
                                  const float* __restrict__ bhh1) {
    int j = blockIdx.x * blockDim.x + threadIdx.x;
    if (j < 400) {
        float v = 0.f, u = 0.f;
        for (int k = 0; k < 100; k++) {
            float w = Wih1[j * 100 + k];
            v += w * W1[k];
            u += w * b1[k];
        }
        g_v1[j] = v;
        g_u1[j] = u + bih1[j] + bhh1[j];
    }
}

// B fill: row n = 4*j + g <- source gate-row (g*100 + j).
// K cols: 0..99 weights, 100 = u1(+u2), 101 = v, 102..103 zero. Single fp16 plane.
__device__ void fill_B(char* sm, const float* __restrict__ W,
                       const float* __restrict__ ua, const float* __restrict__ ub,
                       const float* __restrict__ v, int tid) {
    for (int idx = tid; idx < 400 * 104; idx += NTHREADS) {
        int n = idx / 104, k = idx - n * 104;
        int srow = (n & 3) * 100 + (n >> 2);
        float val = 0.f;
        if (k < 100)       val = W[srow * 100 + k];
        else if (k == 100) { if (ua) val = ua[srow]; if (ub) val += ub[srow]; }
        else if (k == 101) { if (v)  val = v[srow]; }
        *(uint16_t*)(sm + SM_B + n * BSTR + k * 2) =
            __half_as_ushort(__float2half_rn(val));
    }
}

// 1-term fp16 GEMM, fp16 accumulators; warp owns 1 m16 tile x COUNT n8 tiles.
template<int COUNT>
__device__ __forceinline__ void gemm_step(uint32_t acc[7][2],
                                          uint32_t aA, uint32_t aB, int start) {
#pragma unroll
    for (int ch = 0; ch < 7; ch++) {
        uint32_t a[4];
        ldsm_x4(a, aA + ch * 32);
#pragma unroll
        for (int ti = 0; ti < COUNT; ti++) {
            uint32_t b[2];
            ldsm_x2(b, aB + (uint32_t)(start + ti) * (8 * BSTR) + ch * 32);
            mma_f16acc(acc[ti], a, b);
        }
    }
}

// epilogue: packed gate exchange (1 shfl per row-pair reg), cell math, h write.
// Thread cq even holds (i,f) packed; cq odd holds (g,o). Partner = lane^1.
template<int COUNT>
__device__ __forceinline__ void lstm_epi(uint32_t acc[7][2], float creg[2][7],
                                         char* sm, uint32_t Aw,
                                         int start, int grp, int lane) {
    const int cq = lane & 3;
    const int rq = lane >> 2;
    const bool even = (cq & 1) == 0;
    const int row0 = grp * 16 + rq;
#pragma unroll
    for (int ti = 0; ti < COUNT; ti++) {
        uint32_t e0 = __shfl_xor_sync(0xffffffffu, acc[ti][0], 1);
        uint32_t e1 = __shfl_xor_sync(0xffffffffu, acc[ti][1], 1);
        uint32_t rif0 = even ? acc[ti][0] : e0;
        uint32_t rgo0 = even ? e0 : acc[ti][0];
        uint32_t rif1 = even ? acc[ti][1] : e1;
        uint32_t rgo1 = even ? e1 : acc[ti][1];
        int unit = 2 * (start + ti) + (cq >> 1);

        half2 hif0 = *(half2*)&rif0, hgo0 = *(half2*)&rgo0;
        float cc0 = creg[0][ti];
        cc0 = sigf(__low2float(hif0) + 0.f) * 0.f + cc0;  // placeholder removed below
        // row rq
        {
            float gi = __low2float(hif0), gf = __high2float(hif0);
            float gg = __low2float(hgo0), go = __high2float(hgo0);
            float cc = creg[0][ti];
            cc = sigf(gf) * cc + sigf(gi) * tanha(gg);
            creg[0][ti] = cc;
            float h = sigf(go) * tanha(cc);
            *(uint16_t*)(sm + Aw + row0 * ASTR + unit * 2) =
                __half_as_ushort(__float2half_rn(h));
        }
        // row rq + 8
        {
            half2 hif1 = *(half2*)&rif1, hgo1 = *(half2*)&rgo1;
            float gi = __low2float(hif1), gf = __high2float(hif1);
            float gg = __low2float(hgo1), go = __high2float(hgo1);
            float cc = creg[1][ti];
            cc = sigf(gf) * cc + sigf(gi) * tanha(gg);
            creg[1][ti] = cc;
            float h = sigf(go) * tanha(cc);
            *(uint16_t*)(sm + Aw + (row0 + 8) * ASTR + unit * 2) =
                __half_as_ushort(__float2half_rn(h));
        }
    }
}

// ============================ main kernel ============================
__global__ __launch_bounds__(NTHREADS, 1)
void lstm_hmma_kernel(const float* __restrict__ x,
                      const float* __restrict__ Whh1,
                      const float* __restrict__ Wih2,
                      const float* __restrict__ Whh2,
                      const float* __restrict__ bih2,
                      const float* __restrict__ bhh2,
                      const float* __restrict__ W2,
                      const float* __restrict__ b2,
                      float* __restrict__ out) {
    extern __shared__ char sm[];
    const uint32_t smb = sptr(sm);
    const int tid  = threadIdx.x;
    const int warp = tid >> 5;
    const int lane = tid & 31;
    const int b0   = blockIdx.x * MROWS;

    // warp decomposition: 4 M-groups x 8 N-slices
    const int ns  = warp & 7;             // n-slice id
    const int grp = warp >> 3;            // m16 tile id (0..3)
    // slices: ns 0,1 -> 7 tiles; ns 2..7 -> 6 tiles (2*7 + 6*6 = 50)
    const int start = (ns < 2) ? ns * 7 : 14 + (ns - 2) * 6;
    const int count = (ns < 2) ? 7 : 6;

    // ldmatrix lane addresses (A base includes the m16 offset)
    const uint32_t aA0 = smb + SM_A + (uint32_t)grp * (16 * ASTR)
                       + (uint32_t)(lane & 15) * ASTR + ((lane >> 4) ? 16u : 0u);
    const uint32_t aA1 = aA0 + ABUF;
    const uint32_t aB  = smb + SM_B
                       + (uint32_t)(lane & 7) * BSTR + (((lane >> 3) & 1) ? 16u : 0u);

    // ---- prologue ----
    fill_B(sm, Whh1, g_u1, (const float*)nullptr, g_v1, tid);
    for (int i = tid; i < (2 * ABUF) / 4; i += NTHREADS)
        *(uint32_t*)(sm + SM_A + i * 4) = 0u;
    for (int idx = tid; idx < (T_STEPS + 1) * MROWS; idx += NTHREADS) {
        int t = idx >> 6, row = idx & 63;
        float v = (t < T_STEPS) ? x[t * BATCH + b0 + row] : 0.f;
        *(uint16_t*)(sm + SM_X + idx * 2) = __half_as_ushort(__float2half_rn(v));
    }
    for (int i = tid; i < NP * 700; i += NTHREADS)
        *(float*)(sm + SM_W2 + i * 4) = W2[i];
    __syncthreads();
    if (tid < MROWS) {
        *(uint16_t*)(sm + SM_A + tid * ASTR + 200) = 0x3C00u;          // col100 = 1.0
        *(uint16_t*)(sm + SM_A + ABUF + tid * ASTR + 200) = 0x3C00u;
        *(uint16_t*)(sm + SM_A + tid * ASTR + 202) = *(uint16_t*)(sm + SM_X + tid * 2);
    }
    __syncthreads();

    float creg[2][7];
#pragma unroll
    for (int r = 0; r < 2; r++)
#pragma unroll
        for (int ti = 0; ti < 7; ti++) creg[r][ti] = 0.f;

    float y[NP];
#pragma unroll
    for (int q = 0; q < NP; q++) y[q] = 0.f;

    // ==================== layer 1: 30 steps ====================
#pragma unroll 1
    for (int t = 0; t < T_STEPS; t++) {
        const uint32_t rA   = (t & 1) ? aA1 : aA0;
        const uint32_t wOff = SM_A + (uint32_t)((t + 1) & 1) * ABUF;

        uint32_t acc[7][2];
#pragma unroll
        for (int ti = 0; ti < 7; ti++) { acc[ti][0] = 0u; acc[ti][1] = 0u; }

        if (ns < 2) {
            gemm_step<7>(acc, rA, aB, start);
            lstm_epi<7>(acc, creg, sm, wOff, start, grp, lane);
        } else {
            gemm_step<6>(acc, rA, aB, start);
            lstm_epi<6>(acc, creg, sm, wOff, start, grp, lane);
        }
        if (tid < MROWS) {
            *(uint16_t*)(sm + wOff + tid * ASTR + 202) =
                *(uint16_t*)(sm + SM_X + ((t + 1) * MROWS + tid) * 2);
        }
        __syncthreads();
    }
    // h_last now in parity buffer 0 (T_STEPS even)

    // ==================== layer-2 input GEMM (once) ====================
    fill_B(sm, Wih2, bih2, bhh2, (const float*)nullptr, tid);
    __syncthreads();
    {
        uint32_t acc[7][2];
#pragma unroll
        for (int ti = 0; ti < 7; ti++) { acc[ti][0] = 0u; acc[ti][1] = 0u; }
        if (ns < 2) gemm_step<7>(acc, aA0, aB, start);
        else        gemm_step<6>(acc, aA0, aB, start);
        uint2* slot = &g_in2[((size_t)blockIdx.x * NTHREADS + tid) * 7];
        for (int ti = 0; ti < count; ti++)
            slot[ti] = make_uint2(acc[ti][0], acc[ti][1]);
    }
    __syncthreads();
    fill_B(sm, Whh2, (const float*)nullptr, (const float*)nullptr,
           (const float*)nullptr, tid);
    __syncthreads();

    // ==================== layer 2: 7 steps + fused FC2 ====================
    const uint2* slot = &g_in2[((size_t)blockIdx.x * NTHREADS + tid) * 7];
    const float* w2s = (const float*)(sm + SM_W2);
#pragma unroll 1
    for (int ps = 0; ps < NP; ps++) {
        const uint32_t rA   = (ps & 1) ? aA1 : aA0;
        const uint32_t wOff = SM_A + (uint32_t)((ps + 1) & 1) * ABUF;

        uint32_t acc[7][2];
#pragma unroll
        for (int ti = 0; ti < 7; ti++) {
            uint2 v = (ti < count) ? slot[ti] : make_uint2(0u, 0u);
            acc[ti][0] = v.x; acc[ti][1] = v.y;
        }

        if (ns < 2) {
            gemm_step<7>(acc, rA, aB, start);
            lstm_epi<7>(acc, creg, sm, wOff, start, grp, lane);
        } else {
            gemm_step<6>(acc, rA, aB, start);
            lstm_epi<6>(acc, creg, sm, wOff, start, grp, lane);
        }
        __syncthreads();

        // FC2 partial: 128 threads; row = tid/2, j-half = tid%2
        if (tid < 2 * MROWS) {
            int row = tid >> 1;
            int j0  = (tid & 1) * 50;
#pragma unroll 2
            for (int jj = 0; jj < 50; jj++) {
                int j = j0 + jj;
                float h = __half2float(*(const __half*)(sm + wOff + row * ASTR + j * 2));
#pragma unroll
                for (int q = 0; q < NP; q++)
                    y[q] = fmaf(h, w2s[q * 700 + ps * 100 + j], y[q]);
            }
        }
    }

    // ==================== output ====================
    if (tid < 2 * MROWS) {
        int row = tid >> 1;
#pragma unroll
        for (int q = 0; q < NP; q++) {
            float v = y[q] + __shfl_xor_sync(0xffffffffu, y[q], 1);
            if ((tid & 1) == 0)
                out[(size_t)(b0 + row) * NP + q] = sigf(v + b2[q]);
        }
    }
}

// ============================ launch ============================
extern "C" void kernel_launch(void* const* d_in, const int* in_sizes, int n_in,
                              void* d_out, int out_size) {
    const float* x    = (const float*)d_in[0];
    const float* W1   = (const float*)d_in[1];
    const float* b1   = (const float*)d_in[2];
    const float* Wih1 = (const float*)d_in[3];
    const float* Whh1 = (const float*)d_in[4];
    const float* bih1 = (const float*)d_in[5];
    const float* bhh1 = (const float*)d_in[6];
    const float* Wih2 = (const float*)d_in[7];
    const float* Whh2 = (const float*)d_in[8];
    const float* bih2 = (const float*)d_in[9];
    const float* bhh2 = (const float*)d_in[10];
    const float* W2   = (const float*)d_in[11];
    const float* b2   = (const float*)d_in[12];
    float* out = (float*)d_out;

    cudaFuncSetAttribute(lstm_hmma_kernel,
                         cudaFuncAttributeMaxDynamicSharedMemorySize, SMEM_BYTES);

    precompute_kernel<<<1, 512>>>(W1, b1, Wih1, bih1, bhh1);
    lstm_hmma_kernel<<<NCTAS, NTHREADS, SMEM_BYTES>>>(
        x, Whh1, Wih2, Whh2, bih2, bhh2, W2, b2, out);
}

// round 16
// speedup vs baseline: 1.4225x; 1.4225x over previous
#include <cuda_runtime.h>
#include <cuda_fp16.h>
#include <cstdint>

#define T_STEPS 30
#define BATCH   16384
#define NP      7
#define MROWS   128
#define NTHREADS 1024
#define NCTAS   (BATCH / MROWS)     // 128

#define BSTR    208                 // B row stride bytes (104 halves), conflict-free ldsm
#define ASTR    240                 // A(h) row stride bytes (120 halves), conflict-free ldsm
                                    // A cols 102..119 stay ZERO -> annihilate B overread in ch6

// smem byte offsets
#define SM_B   0                    // B: 400 x 208 = 83200 (single fp16 plane)
#define SM_A   83200                // A parity buffers: [A0|A1], each 128*240=30720
#define ABUF   30720
#define SM_W2  144640               // full W2 staged: 4900 floats = 19600
#define SM_X   164240               // staged x: 31 x 128 fp16 = 7936 (slot 30 = 0)
#define SMEM_BYTES 172176

// ---- device scratch (allocation-free) ----
__device__ float g_v1[400];                  // Wih1 @ W1
__device__ float g_u1[400];                  // Wih1 @ b1 + bih1 + bhh1
__device__ uint2 g_in2[(size_t)NCTAS * NTHREADS * 14];  // layer-2 pre-acts, packed fp16 frag

// ============================ helpers ============================
__device__ __forceinline__ uint32_t sptr(const void* p) {
    uint32_t a;
    asm("{ .reg .u64 t; cvta.to.shared.u64 t, %1; cvt.u32.u64 %0, t; }" : "=r"(a) : "l"(p));
    return a;
}
__device__ __forceinline__ float tanha(float x) {
    float y; asm("tanh.approx.f32 %0, %1;" : "=f"(y) : "f"(x)); return y;
}
__device__ __forceinline__ float sigf(float x) { return fmaf(tanha(0.5f * x), 0.5f, 0.5f); }

__device__ __forceinline__ void ldsm_x4(uint32_t* r, uint32_t a) {
    asm volatile("ldmatrix.sync.aligned.m8n8.x4.shared.b16 {%0,%1,%2,%3}, [%4];"
                 : "=r"(r[0]), "=r"(r[1]), "=r"(r[2]), "=r"(r[3]) : "r"(a));
}
__device__ __forceinline__ void ldsm_x2(uint32_t* r, uint32_t a) {
    asm volatile("ldmatrix.sync.aligned.m8n8.x2.shared.b16 {%0,%1}, [%2];"
                 : "=r"(r[0]), "=r"(r[1]) : "r"(a));
}
// fp16-accumulator MMA: D,C are 2 regs (packed halves)
__device__ __forceinline__ void mma_f16acc(uint32_t* d, const uint32_t* a, const uint32_t* b) {
    asm volatile("mma.sync.aligned.m16n8k16.row.col.f16.f16.f16.f16 "
                 "{%0,%1}, {%2,%3,%4,%5}, {%6,%7}, {%0,%1};"
                 : "+r"(d[0]), "+r"(d[1])
                 : "r"(a[0]), "r"(a[1]), "r"(a[2]), "r"(a[3]), "r"(b[0]), "r"(b[1]));
}

// ============================ precompute (tiny) ============================
__global__ void precompute_kernel(const float* __restrict__ W1,
                                  const float* __restrict__ b1,
                                  const float* __restrict__ Wih1,
                                  const float* __restrict__ bih1,
                                  const float* __restrict__ bhh1) {
    int j = blockIdx.x * blockDim.x + threadIdx.x;
    if (j < 400) {
        float v = 0.f, u = 0.f;
        for (int k = 0; k < 100; k++) {
            float w = Wih1[j * 100 + k];
            v += w * W1[k];
            u += w * b1[k];
        }
        g_v1[j] = v;
        g_u1[j] = u + bih1[j] + bhh1[j];
    }
}

// B fill: row n = 4*j + g <- source gate-row (g*100 + j).
// K cols: 0..99 weights, 100 = u1(+u2), 101 = v, 102..103 zero. Single fp16 plane.
__device__ void fill_B(char* sm, const float* __restrict__ W,
                       const float* __restrict__ ua, const float* __restrict__ ub,
                       const float* __restrict__ v, int tid) {
    for (int idx = tid; idx < 400 * 104; idx += NTHREADS) {
        int n = idx / 104, k = idx - n * 104;
        int srow = (n & 3) * 100 + (n >> 2);
        float val = 0.f;
        if (k < 100)       val = W[srow * 100 + k];
        else if (k == 100) { if (ua) val = ua[srow]; if (ub) val += ub[srow]; }
        else if (k == 101) { if (v)  val = v[srow]; }
        *(uint16_t*)(sm + SM_B + n * BSTR + k * 2) =
            __half_as_ushort(__float2half_rn(val));
    }
}

// 1-term fp16 GEMM, fp16 accumulators; warp owns 2 m16 tiles x COUNT n8 tiles.
template<int COUNT>
__device__ __forceinline__ void gemm_step(uint32_t acc[2][7][2],
                                          uint32_t aA, uint32_t aB, int start) {
#pragma unroll
    for (int ch = 0; ch < 7; ch++) {
        uint32_t a[2][4];
#pragma unroll
        for (int mi = 0; mi < 2; mi++)
            ldsm_x4(a[mi], aA + mi * (16 * ASTR) + ch * 32);
#pragma unroll
        for (int ti = 0; ti < COUNT; ti++) {
            uint32_t b[2];
            ldsm_x2(b, aB + (uint32_t)(start + ti) * (8 * BSTR) + ch * 32);
#pragma unroll
            for (int mi = 0; mi < 2; mi++)
                mma_f16acc(acc[mi][ti], a[mi], b);
        }
    }
}

// epilogue (dedup): ONE shfl per (mi,ti); even lane computes row rq, odd row rq+8.
template<int COUNT>
__device__ __forceinline__ void lstm_epi(uint32_t acc[2][7][2], float creg[2][7],
                                         char* sm, uint32_t Aw,
                                         int start, int mtbase, int lane) {
    const int cq = lane & 3;
    const int rq = lane >> 2;
    const bool even = (cq & 1) == 0;
#pragma unroll
    for (int mi = 0; mi < 2; mi++) {
        const int row = (mtbase + mi) * 16 + rq + (even ? 0 : 8);
#pragma unroll
        for (int ti = 0; ti < COUNT; ti++) {
            // even sends reg1 (if of row rq+8, for partner), odd sends reg0 (go of row rq)
            uint32_t sendv = even ? acc[mi][ti][1] : acc[mi][ti][0];
            uint32_t recv  = __shfl_xor_sync(0xffffffffu, sendv, 1);
            uint32_t rif = even ? acc[mi][ti][0] : recv;
            uint32_t rgo = even ? recv : acc[mi][ti][1];
            half2 hif = *(half2*)&rif, hgo = *(half2*)&rgo;
            float gi = __low2float(hif), gf = __high2float(hif);
            float gg = __low2float(hgo), go = __high2float(hgo);
            float cc = creg[mi][ti];
            cc = sigf(gf) * cc + sigf(gi) * tanha(gg);
            creg[mi][ti] = cc;
            float h = sigf(go) * tanha(cc);
            int unit = 2 * (start + ti) + (cq >> 1);
            *(uint16_t*)(sm + Aw + row * ASTR + unit * 2) =
                __half_as_ushort(__float2half_rn(h));
        }
    }
}

// ============================ main kernel ============================
__global__ __launch_bounds__(NTHREADS, 1)
void lstm_hmma_kernel(const float* __restrict__ x,
                      const float* __restrict__ Whh1,
                      const float* __restrict__ Wih2,
                      const float* __restrict__ Whh2,
                      const float* __restrict__ bih2,
                      const float* __restrict__ bhh2,
                      const float* __restrict__ W2,
                      const float* __restrict__ b2,
                      float* __restrict__ out) {
    extern __shared__ char sm[];
    const uint32_t smb = sptr(sm);
    const int tid  = threadIdx.x;
    const int warp = tid >> 5;
    const int lane = tid & 31;
    const int b0   = blockIdx.x * MROWS;

    // warp decomposition: 4 M-groups (2 m16 each) x 8 N-slices
    const int ns     = warp & 7;          // n-slice id
    const int mtbase = (warp >> 3) * 2;   // first m16 tile (0,2,4,6)
    // slices: ns 0,1 -> 7 tiles; ns 2..7 -> 6 tiles (2*7 + 6*6 = 50)
    const int start = (ns < 2) ? ns * 7 : 14 + (ns - 2) * 6;
    const int count = (ns < 2) ? 7 : 6;

    // ldmatrix lane addresses
    const uint32_t aA0 = smb + SM_A + (uint32_t)mtbase * (16 * ASTR)
                       + (uint32_t)(lane & 15) * ASTR + ((lane >> 4) ? 16u : 0u);
    const uint32_t aA1 = aA0 + ABUF;
    const uint32_t aB  = smb + SM_B
                       + (uint32_t)(lane & 7) * BSTR + (((lane >> 3) & 1) ? 16u : 0u);

    // ---- prologue ----
    fill_B(sm, Whh1, g_u1, (const float*)nullptr, g_v1, tid);
    for (int i = tid; i < (2 * ABUF) / 4; i += NTHREADS)
        *(uint32_t*)(sm + SM_A + i * 4) = 0u;
    for (int idx = tid; idx < (T_STEPS + 1) * MROWS; idx += NTHREADS) {
        int t = idx >> 7, row = idx & 127;
        float v = (t < T_STEPS) ? x[t * BATCH + b0 + row] : 0.f;
        *(uint16_t*)(sm + SM_X + idx * 2) = __half_as_ushort(__float2half_rn(v));
    }
    for (int i = tid; i < NP * 700; i += NTHREADS)
        *(float*)(sm + SM_W2 + i * 4) = W2[i];
    __syncthreads();
    if (tid < MROWS) {
        *(uint16_t*)(sm + SM_A + tid * ASTR + 200) = 0x3C00u;          // col100 = 1.0
        *(uint16_t*)(sm + SM_A + ABUF + tid * ASTR + 200) = 0x3C00u;
        *(uint16_t*)(sm + SM_A + tid * ASTR + 202) = *(uint16_t*)(sm + SM_X + tid * 2);
    }
    __syncthreads();

    float creg[2][7];
#pragma unroll
    for (int mi = 0; mi < 2; mi++)
#pragma unroll
        for (int ti = 0; ti < 7; ti++) creg[mi][ti] = 0.f;

    float y[NP];
#pragma unroll
    for (int q = 0; q < NP; q++) y[q] = 0.f;

    // ==================== layer 1: 30 steps ====================
#pragma unroll 1
    for (int t = 0; t < T_STEPS; t++) {
        const uint32_t rA   = (t & 1) ? aA1 : aA0;
        const uint32_t wOff = SM_A + (uint32_t)((t + 1) & 1) * ABUF;

        uint32_t acc[2][7][2];
#pragma unroll
        for (int mi = 0; mi < 2; mi++)
#pragma unroll
            for (int ti = 0; ti < 7; ti++) { acc[mi][ti][0] = 0u; acc[mi][ti][1] = 0u; }

        if (ns < 2) {
            gemm_step<7>(acc, rA, aB, start);
            lstm_epi<7>(acc, creg, sm, wOff, start, mtbase, lane);
        } else {
            gemm_step<6>(acc, rA, aB, start);
            lstm_epi<6>(acc, creg, sm, wOff, start, mtbase, lane);
        }
        if (tid < MROWS) {
            *(uint16_t*)(sm + wOff + tid * ASTR + 202) =
                *(uint16_t*)(sm + SM_X + ((t + 1) * MROWS + tid) * 2);
        }
        __syncthreads();
    }
    // h_last now in parity buffer 0 (T_STEPS even)

    // ==================== layer-2 input GEMM (once) ====================
    fill_B(sm, Wih2, bih2, bhh2, (const float*)nullptr, tid);
    __syncthreads();
    {
        uint32_t acc[2][7][2];
#pragma unroll
        for (int mi = 0; mi < 2; mi++)
#pragma unroll
            for (int ti = 0; ti < 7; ti++) { acc[mi][ti][0] = 0u; acc[mi][ti][1] = 0u; }
        if (ns < 2) gemm_step<7>(acc, aA0, aB, start);
        else        gemm_step<6>(acc, aA0, aB, start);
        uint2* slot = &g_in2[((size_t)blockIdx.x * NTHREADS + tid) * 14];
#pragma unroll
        for (int mi = 0; mi < 2; mi++)
            for (int ti = 0; ti < count; ti++)
                slot[mi * 7 + ti] = make_uint2(acc[mi][ti][0], acc[mi][ti][1]);
    }
    __syncthreads();
    fill_B(sm, Whh2, (const float*)nullptr, (const float*)nullptr,
           (const float*)nullptr, tid);
    __syncthreads();

    // ==================== layer 2: 7 steps + fused FC2 ====================
    const uint2* slot = &g_in2[((size_t)blockIdx.x * NTHREADS + tid) * 14];
    const float* w2s = (const float*)(sm + SM_W2);
#pragma unroll 1
    for (int ps = 0; ps < NP; ps++) {
        const uint32_t rA   = (ps & 1) ? aA1 : aA0;
        const uint32_t wOff = SM_A + (uint32_t)((ps + 1) & 1) * ABUF;

        uint32_t acc[2][7][2];
#pragma unroll
        for (int mi = 0; mi < 2; mi++)
#pragma unroll
            for (int ti = 0; ti < 7; ti++) {
                uint2 v = (ti < count) ? slot[mi * 7 + ti] : make_uint2(0u, 0u);
                acc[mi][ti][0] = v.x; acc[mi][ti][1] = v.y;
            }

        if (ns < 2) {
            gemm_step<7>(acc, rA, aB, start);
            lstm_epi<7>(acc, creg, sm, wOff, start, mtbase, lane);
        } else {
            gemm_step<6>(acc, rA, aB, start);
            lstm_epi<6>(acc, creg, sm, wOff, start, mtbase, lane);
        }
        __syncthreads();

        // FC2 partial: 256 threads; row = tid/2, j-half = tid%2
        if (tid < 2 * MROWS) {
            int row = tid >> 1;
            int j0  = (tid & 1) * 50;
#pragma unroll 2
            for (int jj = 0; jj < 50; jj++) {
                int j = j0 + jj;
                float h = __half2float(*(const __half*)(sm + wOff + row * ASTR + j * 2));
#pragma unroll
                for (int q = 0; q < NP; q++)
                    y[q] = fmaf(h, w2s[q * 700 + ps * 100 + j], y[q]);
            }
        }
    }

    // ==================== output ====================
    if (tid < 2 * MROWS) {
        int row = tid >> 1;
#pragma unroll
        for (int q = 0; q < NP; q++) {
            float v = y[q] + __shfl_xor_sync(0xffffffffu, y[q], 1);
            if ((tid & 1) == 0)
                out[(size_t)(b0 + row) * NP + q] = sigf(v + b2[q]);
        }
    }
}

// ============================ launch ============================
extern "C" void kernel_launch(void* const* d_in, const int* in_sizes, int n_in,
                              void* d_out, int out_size) {
    const float* x    = (const float*)d_in[0];
    const float* W1   = (const float*)d_in[1];
    const float* b1   = (const float*)d_in[2];
    const float* Wih1 = (const float*)d_in[3];
    const float* Whh1 = (const float*)d_in[4];
    const float* bih1 = (const float*)d_in[5];
    const float* bhh1 = (const float*)d_in[6];
    const float* Wih2 = (const float*)d_in[7];
    const float* Whh2 = (const float*)d_in[8];
    const float* bih2 = (const float*)d_in[9];
    const float* bhh2 = (const float*)d_in[10];
    const float* W2   = (const float*)d_in[11];
    const float* b2   = (const float*)d_in[12];
    float* out = (float*)d_out;

    cudaFuncSetAttribute(lstm_hmma_kernel,
                         cudaFuncAttributeMaxDynamicSharedMemorySize, SMEM_BYTES);

    precompute_kernel<<<1, 512>>>(W1, b1, Wih1, bih1, bhh1);
    lstm_hmma_kernel<<<NCTAS, NTHREADS, SMEM_BYTES>>>(
        x, Whh1, Wih2, Whh2, bih2, bhh2, W2, b2, out);
}

// round 17
// speedup vs baseline: 1.4372x; 1.0103x over previous
#include <cuda_runtime.h>
#include <cuda_fp16.h>
#include <cstdint>

#define T_STEPS 30
#define BATCH   16384
#define NP      7
#define MROWS   128
#define NTHREADS 1024
#define NCTAS   (BATCH / MROWS)     // 128

#define BSTR    208                 // B row stride bytes (104 halves), conflict-free ldsm
#define ASTR    240                 // A(h) row stride bytes (120 halves), conflict-free ldsm
                                    // A cols 102..119 stay ZERO -> annihilate B overread in ch6

// smem byte offsets
#define SM_B   0                    // B: 400 x 208 = 83200 (single fp16 plane)
#define SM_A   83200                // A parity buffers: [A0|A1], each 128*240=30720
#define ABUF   30720
#define SM_W2  144640               // full W2 staged: 4900 floats = 19600
#define SM_X   164240               // staged x: 31 x 128 fp16 = 7936 (slot 30 = 0)
#define SMEM_BYTES 172176

// ---- device scratch (allocation-free) ----
__device__ float g_v1[400];                  // Wih1 @ W1
__device__ float g_u1[400];                  // Wih1 @ b1 + bih1 + bhh1
__device__ uint2 g_in2[(size_t)NCTAS * NTHREADS * 14];  // layer-2 pre-acts, packed fp16 frag

// ============================ helpers ============================
__device__ __forceinline__ uint32_t sptr(const void* p) {
    uint32_t a;
    asm("{ .reg .u64 t; cvta.to.shared.u64 t, %1; cvt.u32.u64 %0, t; }" : "=r"(a) : "l"(p));
    return a;
}
__device__ __forceinline__ float tanha(float x) {
    float y; asm("tanh.approx.f32 %0, %1;" : "=f"(y) : "f"(x)); return y;
}
__device__ __forceinline__ float sigf(float x) { return fmaf(tanha(0.5f * x), 0.5f, 0.5f); }
__device__ __forceinline__ uint32_t tanh2(uint32_t v) {
    uint32_t y; asm("tanh.approx.f16x2 %0, %1;" : "=r"(y) : "r"(v)); return y;
}
__device__ __forceinline__ uint32_t hmul2u(uint32_t a, uint32_t b) {
    uint32_t d;
    asm("mul.f16x2 %0, %1, %2;" : "=r"(d) : "r"(a), "r"(b));
    return d;
}
__device__ __forceinline__ uint32_t hfma2u(uint32_t a, uint32_t b, uint32_t c) {
    uint32_t d;
    asm("fma.rn.f16x2 %0, %1, %2, %3;" : "=r"(d) : "r"(a), "r"(b), "r"(c));
    return d;
}

__device__ __forceinline__ void ldsm_x4(uint32_t* r, uint32_t a) {
    asm volatile("ldmatrix.sync.aligned.m8n8.x4.shared.b16 {%0,%1,%2,%3}, [%4];"
                 : "=r"(r[0]), "=r"(r[1]), "=r"(r[2]), "=r"(r[3]) : "r"(a));
}
__device__ __forceinline__ void ldsm_x2(uint32_t* r, uint32_t a) {
    asm volatile("ldmatrix.sync.aligned.m8n8.x2.shared.b16 {%0,%1}, [%2];"
                 : "=r"(r[0]), "=r"(r[1]) : "r"(a));
}
// fp16-accumulator MMA: D,C are 2 regs (packed halves)
__device__ __forceinline__ void mma_f16acc(uint32_t* d, const uint32_t* a, const uint32_t* b) {
    asm volatile("mma.sync.aligned.m16n8k16.row.col.f16.f16.f16.f16 "
                 "{%0,%1}, {%2,%3,%4,%5}, {%6,%7}, {%0,%1};"
                 : "+r"(d[0]), "+r"(d[1])
                 : "r"(a[0]), "r"(a[1]), "r"(a[2]), "r"(a[3]), "r"(b[0]), "r"(b[1]));
}

// ============================ precompute (tiny) ============================
__global__ void precompute_kernel(const float* __restrict__ W1,
                                  const float* __restrict__ b1,
                                  const float* __restrict__ Wih1,
                                  const float* __restrict__ bih1,
                                  const float* __restrict__ bhh1) {
    int j = blockIdx.x * blockDim.x + threadIdx.x;
    if (j < 400) {
        float v = 0.f, u = 0.f;
        for (int k = 0; k < 100; k++) {
            float w = Wih1[j * 100 + k];
            v += w * W1[k];
            u += w * b1[k];
        }
        g_v1[j] = v;
        g_u1[j] = u + bih1[j] + bhh1[j];
    }
}

// B fill: row n = 4*j + g <- source gate-row (g*100 + j).
// K cols: 0..99 weights, 100 = u1(+u2), 101 = v, 102..103 zero. Single fp16 plane.
__device__ void fill_B(char* sm, const float* __restrict__ W,
                       const float* __restrict__ ua, const float* __restrict__ ub,
                       const float* __restrict__ v, int tid) {
    for (int idx = tid; idx < 400 * 104; idx += NTHREADS) {
        int n = idx / 104, k = idx - n * 104;
        int srow = (n & 3) * 100 + (n >> 2);
        float val = 0.f;
        if (k < 100)       val = W[srow * 100 + k];
        else if (k == 100) { if (ua) val = ua[srow]; if (ub) val += ub[srow]; }
        else if (k == 101) { if (v)  val = v[srow]; }
        *(uint16_t*)(sm + SM_B + n * BSTR + k * 2) =
            __half_as_ushort(__float2half_rn(val));
    }
}

// 1-term fp16 GEMM, fp16 accumulators; warp owns 2 m16 tiles x COUNT n8 tiles.
template<int COUNT>
__device__ __forceinline__ void gemm_step(uint32_t acc[2][7][2],
                                          uint32_t aA, uint32_t aB, int start) {
#pragma unroll
    for (int ch = 0; ch < 7; ch++) {
        uint32_t a[2][4];
#pragma unroll
        for (int mi = 0; mi < 2; mi++)
            ldsm_x4(a[mi], aA + mi * (16 * ASTR) + ch * 32);
#pragma unroll
        for (int ti = 0; ti < COUNT; ti++) {
            uint32_t b[2];
            ldsm_x2(b, aB + (uint32_t)(start + ti) * (8 * BSTR) + ch * 32);
#pragma unroll
            for (int mi = 0; mi < 2; mi++)
                mma_f16acc(acc[mi][ti], a[mi], b);
        }
    }
}

// epilogue (dedup + f16x2 MUFU): ONE shfl per (mi,ti); even lane row rq, odd row rq+8.
// 3 MUFU/cell: tanh2(0.5*(i,f)), tanh2((g, 0.5*o)), tanh.f32(c_new).
template<int COUNT>
__device__ __forceinline__ void lstm_epi(uint32_t acc[2][7][2], float creg[2][7],
                                         char* sm, uint32_t Aw,
                                         int start, int mtbase, int lane) {
    const int cq = lane & 3;
    const int rq = lane >> 2;
    const bool even = (cq & 1) == 0;
    const uint32_t H2_05_05 = 0x38003800u;   // (lo=0.5, hi=0.5)
    const uint32_t H2_1_05  = 0x38003C00u;   // (lo=1.0, hi=0.5)
#pragma unroll
    for (int mi = 0; mi < 2; mi++) {
        const int row = (mtbase + mi) * 16 + rq + (even ? 0 : 8);
#pragma unroll
        for (int ti = 0; ti < COUNT; ti++) {
            // even sends reg1 (row rq+8 data for partner), odd sends reg0 (row rq data)
            uint32_t sendv = even ? acc[mi][ti][1] : acc[mi][ti][0];
            uint32_t recv  = __shfl_xor_sync(0xffffffffu, sendv, 1);
            uint32_t rif = even ? acc[mi][ti][0] : recv;   // (gi, gf) packed
            uint32_t rgo = even ? recv : acc[mi][ti][1];   // (gg, go) packed

            uint32_t s_if = hfma2u(tanh2(hmul2u(rif, H2_05_05)), H2_05_05, H2_05_05);
            uint32_t t_go = tanh2(hmul2u(rgo, H2_1_05));   // (tanh_g, tanh(go/2))

            half2 h_sif = *(half2*)&s_if;
            half2 h_tgo = *(half2*)&t_go;
            float sig_i  = __low2float(h_sif);
            float sig_f  = __high2float(h_sif);
            float tanh_g = __low2float(h_tgo);
            float sig_o  = fmaf(__high2float(h_tgo), 0.5f, 0.5f);

            float cc = creg[mi][ti];
            cc = sig_f * cc + sig_i * tanh_g;
            creg[mi][ti] = cc;
            float h = sig_o * tanha(cc);
            int unit = 2 * (start + ti) + (cq >> 1);
            *(uint16_t*)(sm + Aw + row * ASTR + unit * 2) =
                __half_as_ushort(__float2half_rn(h));
        }
    }
}

// ============================ main kernel ============================
__global__ __launch_bounds__(NTHREADS, 1)
void lstm_hmma_kernel(const float* __restrict__ x,
                      const float* __restrict__ Whh1,
                      const float* __restrict__ Wih2,
                      const float* __restrict__ Whh2,
                      const float* __restrict__ bih2,
                      const float* __restrict__ bhh2,
                      const float* __restrict__ W2,
                      const float* __restrict__ b2,
                      float* __restrict__ out) {
    extern __shared__ char sm[];
    const uint32_t smb = sptr(sm);
    const int tid  = threadIdx.x;
    const int warp = tid >> 5;
    const int lane = tid & 31;
    const int b0   = blockIdx.x * MROWS;

    // warp decomposition: 4 M-groups (2 m16 each) x 8 N-slices
    const int ns     = warp & 7;          // n-slice id
    const int mtbase = (warp >> 3) * 2;   // first m16 tile (0,2,4,6)
    // slices: ns 0,1 -> 7 tiles; ns 2..7 -> 6 tiles (2*7 + 6*6 = 50)
    const int start = (ns < 2) ? ns * 7 : 14 + (ns - 2) * 6;
    const int count = (ns < 2) ? 7 : 6;

    // ldmatrix lane addresses
    const uint32_t aA0 = smb + SM_A + (uint32_t)mtbase * (16 * ASTR)
                       + (uint32_t)(lane & 15) * ASTR + ((lane >> 4) ? 16u : 0u);
    const uint32_t aA1 = aA0 + ABUF;
    const uint32_t aB  = smb + SM_B
                       + (uint32_t)(lane & 7) * BSTR + (((lane >> 3) & 1) ? 16u : 0u);

    // ---- prologue ----
    fill_B(sm, Whh1, g_u1, (const float*)nullptr, g_v1, tid);
    for (int i = tid; i < (2 * ABUF) / 4; i += NTHREADS)
        *(uint32_t*)(sm + SM_A + i * 4) = 0u;
    for (int idx = tid; idx < (T_STEPS + 1) * MROWS; idx += NTHREADS) {
        int t = idx >> 7, row = idx & 127;
        float v = (t < T_STEPS) ? x[t * BATCH + b0 + row] : 0.f;
        *(uint16_t*)(sm + SM_X + idx * 2) = __half_as_ushort(__float2half_rn(v));
    }
    for (int i = tid; i < NP * 700; i += NTHREADS)
        *(float*)(sm + SM_W2 + i * 4) = W2[i];
    __syncthreads();
    if (tid < MROWS) {
        *(uint16_t*)(sm + SM_A + tid * ASTR + 200) = 0x3C00u;          // col100 = 1.0
        *(uint16_t*)(sm + SM_A + ABUF + tid * ASTR + 200) = 0x3C00u;
        *(uint16_t*)(sm + SM_A + tid * ASTR + 202) = *(uint16_t*)(sm + SM_X + tid * 2);
    }
    __syncthreads();

    float creg[2][7];
#pragma unroll
    for (int mi = 0; mi < 2; mi++)
#pragma unroll
        for (int ti = 0; ti < 7; ti++) creg[mi][ti] = 0.f;

    float y[NP];
#pragma unroll
    for (int q = 0; q < NP; q++) y[q] = 0.f;

    // ==================== layer 1: 30 steps ====================
#pragma unroll 1
    for (int t = 0; t < T_STEPS; t++) {
        const uint32_t rA   = (t & 1) ? aA1 : aA0;
        const uint32_t wOff = SM_A + (uint32_t)((t + 1) & 1) * ABUF;

        uint32_t acc[2][7][2];
#pragma unroll
        for (int mi = 0; mi < 2; mi++)
#pragma unroll
            for (int ti = 0; ti < 7; ti++) { acc[mi][ti][0] = 0u; acc[mi][ti][1] = 0u; }

        if (ns < 2) {
            gemm_step<7>(acc, rA, aB, start);
            lstm_epi<7>(acc, creg, sm, wOff, start, mtbase, lane);
        } else {
            gemm_step<6>(acc, rA, aB, start);
            lstm_epi<6>(acc, creg, sm, wOff, start, mtbase, lane);
        }
        if (tid < MROWS) {
            *(uint16_t*)(sm + wOff + tid * ASTR + 202) =
                *(uint16_t*)(sm + SM_X + ((t + 1) * MROWS + tid) * 2);
        }
        __syncthreads();
    }
    // h_last now in parity buffer 0 (T_STEPS even)

    // ==================== layer-2 input GEMM (once) ====================
    fill_B(sm, Wih2, bih2, bhh2, (const float*)nullptr, tid);
    __syncthreads();
    {
        uint32_t acc[2][7][2];
#pragma unroll
        for (int mi = 0; mi < 2; mi++)
#pragma unroll
            for (int ti = 0; ti < 7; ti++) { acc[mi][ti][0] = 0u; acc[mi][ti][1] = 0u; }
        if (ns < 2) gemm_step<7>(acc, aA0, aB, start);
        else        gemm_step<6>(acc, aA0, aB, start);
        uint2* slot = &g_in2[((size_t)blockIdx.x * NTHREADS + tid) * 14];
#pragma unroll
        for (int mi = 0; mi < 2; mi++)
            for (int ti = 0; ti < count; ti++)
                slot[mi * 7 + ti] = make_uint2(acc[mi][ti][0], acc[mi][ti][1]);
    }
    __syncthreads();
    fill_B(sm, Whh2, (const float*)nullptr, (const float*)nullptr,
           (const float*)nullptr, tid);
    __syncthreads();

    // ==================== layer 2: 7 steps + fused FC2 ====================
    const uint2* slot = &g_in2[((size_t)blockIdx.x * NTHREADS + tid) * 14];
    const float* w2s = (const float*)(sm + SM_W2);
#pragma unroll 1
    for (int ps = 0; ps < NP; ps++) {
        const uint32_t rA   = (ps & 1) ? aA1 : aA0;
        const uint32_t wOff = SM_A + (uint32_t)((ps + 1) & 1) * ABUF;

        uint32_t acc[2][7][2];
#pragma unroll
        for (int mi = 0; mi < 2; mi++)
#pragma unroll
            for (int ti = 0; ti < 7; ti++) {
                uint2 v = (ti < count) ? slot[mi * 7 + ti] : make_uint2(0u, 0u);
                acc[mi][ti][0] = v.x; acc[mi][ti][1] = v.y;
            }

        if (ns < 2) {
            gemm_step<7>(acc, rA, aB, start);
            lstm_epi<7>(acc, creg, sm, wOff, start, mtbase, lane);
        } else {
            gemm_step<6>(acc, rA, aB, start);
            lstm_epi<6>(acc, creg, sm, wOff, start, mtbase, lane);
        }
        __syncthreads();

        // FC2 partial: 256 threads; row = tid/2, j-half = tid%2
        if (tid < 2 * MROWS) {
            int row = tid >> 1;
            int j0  = (tid & 1) * 50;
#pragma unroll 2
            for (int jj = 0; jj < 50; jj++) {
                int j = j0 + jj;
                float h = __half2float(*(const __half*)(sm + wOff + row * ASTR + j * 2));
#pragma unroll
                for (int q = 0; q < NP; q++)
                    y[q] = fmaf(h, w2s[q * 700 + ps * 100 + j], y[q]);
            }
        }
    }

    // ==================== output ====================
    if (tid < 2 * MROWS) {
        int row = tid >> 1;
#pragma unroll
        for (int q = 0; q < NP; q++) {
            float v = y[q] + __shfl_xor_sync(0xffffffffu, y[q], 1);
            if ((tid & 1) == 0)
                out[(size_t)(b0 + row) * NP + q] = sigf(v + b2[q]);
        }
    }
}

// ============================ launch ============================
extern "C" void kernel_launch(void* const* d_in, const int* in_sizes, int n_in,
                              void* d_out, int out_size) {
    const float* x    = (const float*)d_in[0];
    const float* W1   = (const float*)d_in[1];
    const float* b1   = (const float*)d_in[2];
    const float* Wih1 = (const float*)d_in[3];
    const float* Whh1 = (const float*)d_in[4];
    const float* bih1 = (const float*)d_in[5];
    const float* bhh1 = (const float*)d_in[6];
    const float* Wih2 = (const float*)d_in[7];
    const float* Whh2 = (const float*)d_in[8];
    const float* bih2 = (const float*)d_in[9];
    const float* bhh2 = (const float*)d_in[10];
    const float* W2   = (const float*)d_in[11];
    const float* b2   = (const float*)d_in[12];
    float* out = (float*)d_out;

    cudaFuncSetAttribute(lstm_hmma_kernel,
                         cudaFuncAttributeMaxDynamicSharedMemorySize, SMEM_BYTES);

    precompute_kernel<<<1, 512>>>(W1, b1, Wih1, bih1, bhh1);
    lstm_hmma_kernel<<<NCTAS, NTHREADS, SMEM_BYTES>>>(
        x, Whh1, Wih2, Whh2, bih2, bhh2, W2, b2, out);
}